// round 2
// baseline (speedup 1.0000x reference)
#include <cuda_runtime.h>
#include <cstddef>

// Problem constants
#define BB 512   // batch
#define TT 512   // timesteps
#define FF 64    // input features
#define H1 128   // layer1 hidden
#define G1 512   // 4*H1
#define H2 64    // layer2 hidden
#define G2 256   // 4*H2

typedef unsigned long long u64;

// ---------------------------------------------------------------------------
// Packed fp32x2 helpers (sm_103a): 2 IEEE fp32 FMAs per instruction.
// ---------------------------------------------------------------------------
__device__ __forceinline__ u64 pack2(float lo, float hi) {
    u64 r; asm("mov.b64 %0, {%1, %2};" : "=l"(r) : "f"(lo), "f"(hi)); return r;
}
__device__ __forceinline__ float2 unpack2(u64 v) {
    float2 f; asm("mov.b64 {%0, %1}, %2;" : "=f"(f.x), "=f"(f.y) : "l"(v)); return f;
}
__device__ __forceinline__ void fma2(u64& d, u64 a, u64 b) {
    asm("fma.rn.f32x2 %0, %1, %2, %0;" : "+l"(d) : "l"(a), "l"(b));
}
__device__ __forceinline__ void add2(u64& d, u64 a) {
    asm("add.rn.f32x2 %0, %0, %1;" : "+l"(d) : "l"(a));
}

// ---------------------------------------------------------------------------
// Device scratch
// ---------------------------------------------------------------------------
__device__ float g_Wp1[FF * G1];        // W1 permuted: [f][j*4+gate]
__device__ float g_bp1[G1];
__device__ float g_Up1[H1 * G1];        // U1 permuted: [k][j*4+gate]
__device__ float g_Wp2[H1 * G2];
__device__ float g_bp2[G2];
__device__ float g_Up2[H2 * G2];
__device__ float g_xw1[(size_t)TT * BB * G1];  // [t][b][j*4+gate]
__device__ float g_h1[(size_t)TT * BB * H1];   // [t][b][j]
__device__ float g_xw2[(size_t)TT * BB * G2];  // [t][b][j*4+gate]
__device__ float g_h2[BB * H2];                // final layer2 h

__device__ __forceinline__ float sigf(float x) {
    return __fdividef(1.0f, 1.0f + __expf(-x));
}

// ---------------------------------------------------------------------------
// Prep: permute weights so column n = j*4 + gate  (gate order i,f,g,o)
// ---------------------------------------------------------------------------
__global__ void prep_kernel(const float* __restrict__ W1, const float* __restrict__ U1,
                            const float* __restrict__ b1, const float* __restrict__ W2,
                            const float* __restrict__ U2, const float* __restrict__ b2)
{
    int i = blockIdx.x * blockDim.x + threadIdx.x;
    if (i < FF * G1) {
        int f = i >> 9, n = i & 511;
        int j = n >> 2, gi = n & 3;
        g_Wp1[i] = W1[f * G1 + gi * H1 + j];
    }
    if (i < G1) {
        int j = i >> 2, gi = i & 3;
        g_bp1[i] = b1[gi * H1 + j];
    }
    if (i < H1 * G1) {
        int k = i >> 9, n = i & 511;
        int j = n >> 2, gi = n & 3;
        g_Up1[i] = U1[k * G1 + gi * H1 + j];
    }
    if (i < H1 * G2) {
        int k = i >> 8, n = i & 255;
        int j = n >> 2, gi = n & 3;
        g_Wp2[i] = W2[k * G2 + gi * H2 + j];
    }
    if (i < G2) {
        int j = i >> 2, gi = i & 3;
        g_bp2[i] = b2[gi * H2 + j];
    }
    if (i < H2 * G2) {
        int k = i >> 8, n = i & 255;
        int j = n >> 2, gi = n & 3;
        g_Up2[i] = U2[k * G2 + gi * H2 + j];
    }
}

// ---------------------------------------------------------------------------
// Tiled GEMM with f32x2:  C[m][n] = sum_k A_row(m)[k] * W[k][n] + bias[n]
// CTA tile 128(m) x 64(n); A tile in smem as DUPLICATED pairs {a,a} so the
// m-broadcast operand is pre-packed; W pairs come free from LDS.128.
// ---------------------------------------------------------------------------
#define AS2_LD 260   // floats per k-row of duplicated A tile (mult of 4, conflict-padded)
#define GEMM_SMEM ((64 * AS2_LD + 64 * 64) * 4)

__global__ __launch_bounds__(256) void gemm_kernel(
    const float* __restrict__ A, const float* __restrict__ W,
    const float* __restrict__ bias, float* __restrict__ C,
    int sT, int sB, int K, int N)
{
    extern __shared__ float sm[];
    float* As2 = sm;                 // [64][AS2_LD]: col 2m,2m+1 = A[m][k] duplicated
    float* Ws  = sm + 64 * AS2_LD;   // [64][64]
    const int tid = threadIdx.x;
    const int tx = tid & 15, ty = tid >> 4;
    const int mt = blockIdx.x * 128;
    const int nt = blockIdx.y * 64;

    u64 acc2[8][2];
#pragma unroll
    for (int q = 0; q < 8; q++) { acc2[q][0] = 0ull; acc2[q][1] = 0ull; }

    for (int kt = 0; kt < K; kt += 64) {
        // A tile: 128 rows x 64 k, transposed + duplicated into smem
#pragma unroll
        for (int i = 0; i < 8; i++) {
            int li = tid + i * 256;
            int m  = li >> 4;
            int c4 = (li & 15) << 2;
            int gm = mt + m;
            int t  = gm >> 9;
            int b  = gm & 511;
            float4 v = *(const float4*)(A + (size_t)t * sT + (size_t)b * sB + kt + c4);
            *(float2*)(As2 + (c4 + 0) * AS2_LD + (m << 1)) = make_float2(v.x, v.x);
            *(float2*)(As2 + (c4 + 1) * AS2_LD + (m << 1)) = make_float2(v.y, v.y);
            *(float2*)(As2 + (c4 + 2) * AS2_LD + (m << 1)) = make_float2(v.z, v.z);
            *(float2*)(As2 + (c4 + 3) * AS2_LD + (m << 1)) = make_float2(v.w, v.w);
        }
        // W tile: 64 k x 64 n
#pragma unroll
        for (int i = 0; i < 4; i++) {
            int li = tid + i * 256;
            int k  = li >> 4;
            int c4 = (li & 15) << 2;
            *(float4*)(Ws + k * 64 + c4) = *(const float4*)(W + (size_t)(kt + k) * N + nt + c4);
        }
        __syncthreads();
#pragma unroll 8
        for (int k = 0; k < 64; k++) {
            const float* arow = As2 + k * AS2_LD;
            ulonglong2 aA = *(const ulonglong2*)(arow + (ty << 3));          // m=4ty,4ty+1 dup
            ulonglong2 aB = *(const ulonglong2*)(arow + (ty << 3) + 4);      // m=4ty+2,4ty+3
            ulonglong2 aC = *(const ulonglong2*)(arow + 128 + (ty << 3));    // m=64+4ty..
            ulonglong2 aD = *(const ulonglong2*)(arow + 128 + (ty << 3) + 4);
            ulonglong2 wv = *(const ulonglong2*)(Ws + (k << 6) + (tx << 2)); // {n0,n1},{n2,n3}
            fma2(acc2[0][0], aA.x, wv.x); fma2(acc2[0][1], aA.x, wv.y);
            fma2(acc2[1][0], aA.y, wv.x); fma2(acc2[1][1], aA.y, wv.y);
            fma2(acc2[2][0], aB.x, wv.x); fma2(acc2[2][1], aB.x, wv.y);
            fma2(acc2[3][0], aB.y, wv.x); fma2(acc2[3][1], aB.y, wv.y);
            fma2(acc2[4][0], aC.x, wv.x); fma2(acc2[4][1], aC.x, wv.y);
            fma2(acc2[5][0], aC.y, wv.x); fma2(acc2[5][1], aC.y, wv.y);
            fma2(acc2[6][0], aD.x, wv.x); fma2(acc2[6][1], aD.x, wv.y);
            fma2(acc2[7][0], aD.y, wv.x); fma2(acc2[7][1], aD.y, wv.y);
        }
        __syncthreads();
    }
    ulonglong2 bp = *(const ulonglong2*)(bias + nt + (tx << 2));
#pragma unroll
    for (int q = 0; q < 8; q++) {
        int m = mt + ((q < 4) ? ((ty << 2) + q) : (64 + (ty << 2) + q - 4));
        add2(acc2[q][0], bp.x);
        add2(acc2[q][1], bp.y);
        *(ulonglong2*)(C + (size_t)m * N + nt + (tx << 2)) =
            make_ulonglong2(acc2[q][0], acc2[q][1]);
    }
}

// ---------------------------------------------------------------------------
// Layer-1 recurrence (f32x2). 128 CTAs x 256 threads; CTA owns 4 batch rows.
// thread = (j in [0,128), ks in {0,1}); ks splits the K=128 reduction.
// Per ks-half: 32 U rows in smem, 32 in registers. h kept in smem as
// duplicated pairs {h,h} so the broadcast operand is pre-packed.
// Per k-row: 1 LDS.128 (U gate pairs) + 2 bcast LDS.128 (h dup) + 8 FMA2.
// ---------------------------------------------------------------------------
#define REC1_SMEM ((64 * 512 + 2 * 128 * 8 + 128 * 20) * 4)  // 149504 B

__global__ __launch_bounds__(256, 1) void rec1_kernel()
{
    extern __shared__ float sm[];
    float* Us = sm;                  // [64][512]: s<32 -> k=s (ks0), s>=32 -> k=s+32 (ks1)
    float* hd = sm + 64 * 512;       // [2][128][8]: per k-row {h0,h0,h1,h1,h2,h2,h3,h3}
    float* ex = hd + 2 * 128 * 8;    // [128][20]: ks=1 partials (padded stride)

    const int tid  = threadIdx.x;
    const int j    = tid & 127;
    const int ks   = tid >> 7;
    const int brow = blockIdx.x << 2;

    // cooperative load of smem-resident U rows
    for (int i = tid; i < 64 * 128; i += 256) {
        int s = i >> 7;
        int c = (i & 127) << 2;
        int krow = (s < 32) ? s : (s + 32);
        *(float4*)(Us + s * 512 + c) = *(const float4*)(g_Up1 + krow * 512 + c);
    }
    // register-resident U rows (gate pairs)
    const int rbase = ks * 64 + 32;
    ulonglong2 uw[32];
#pragma unroll
    for (int r = 0; r < 32; r++)
        uw[r] = *(const ulonglong2*)(g_Up1 + (rbase + r) * 512 + (j << 2));
    for (int i = tid; i < 2 * 128 * 8; i += 256) hd[i] = 0.f;  // h0 = 0
    float cc[4] = {0.f, 0.f, 0.f, 0.f};
    __syncthreads();

    const float* up0 = Us + (ks * 32) * 512 + (j << 2);
    int buf = 0;
    for (int t = 0; t < TT; t++) {
        u64 z2[4][2];
#pragma unroll
        for (int b = 0; b < 4; b++) { z2[b][0] = 0ull; z2[b][1] = 0ull; }

        ulonglong2 xv[4];
        if (ks == 0) {  // issue early; consumed after the FMA loop
#pragma unroll
            for (int b = 0; b < 4; b++)
                xv[b] = *(const ulonglong2*)(g_xw1 + ((size_t)(t * BB + brow + b) << 9) + (j << 2));
        }

        const float* hb = hd + buf * 1024;
        {   // smem U rows: k = ks*64 + [0,32)
            const float* hp = hb + (ks * 64) * 8;
            const float* up = up0;
#pragma unroll 4
            for (int r = 0; r < 32; r++) {
                ulonglong2 hA = *(const ulonglong2*)(hp + (r << 3));      // {h0,h0},{h1,h1}
                ulonglong2 hB = *(const ulonglong2*)(hp + (r << 3) + 4);  // {h2,h2},{h3,h3}
                ulonglong2 uv = *(const ulonglong2*)(up);
                up += 512;
                fma2(z2[0][0], hA.x, uv.x); fma2(z2[0][1], hA.x, uv.y);
                fma2(z2[1][0], hA.y, uv.x); fma2(z2[1][1], hA.y, uv.y);
                fma2(z2[2][0], hB.x, uv.x); fma2(z2[2][1], hB.x, uv.y);
                fma2(z2[3][0], hB.y, uv.x); fma2(z2[3][1], hB.y, uv.y);
            }
        }
        {   // register U rows: k = ks*64 + [32,64)
            const float* hp = hb + rbase * 8;
#pragma unroll
            for (int r = 0; r < 32; r++) {
                ulonglong2 hA = *(const ulonglong2*)(hp + (r << 3));
                ulonglong2 hB = *(const ulonglong2*)(hp + (r << 3) + 4);
                fma2(z2[0][0], hA.x, uw[r].x); fma2(z2[0][1], hA.x, uw[r].y);
                fma2(z2[1][0], hA.y, uw[r].x); fma2(z2[1][1], hA.y, uw[r].y);
                fma2(z2[2][0], hB.x, uw[r].x); fma2(z2[2][1], hB.x, uw[r].y);
                fma2(z2[3][0], hB.y, uw[r].x); fma2(z2[3][1], hB.y, uw[r].y);
            }
        }
        if (ks) {
#pragma unroll
            for (int b = 0; b < 4; b++)
                *(ulonglong2*)(ex + j * 20 + (b << 2)) = make_ulonglong2(z2[b][0], z2[b][1]);
        }
        __syncthreads();
        if (ks == 0) {
            float* hn = hd + (buf ^ 1) * 1024;
            float hv[4];
#pragma unroll
            for (int b = 0; b < 4; b++) {
                ulonglong2 e = *(const ulonglong2*)(ex + j * 20 + (b << 2));
                add2(z2[b][0], e.x);
                add2(z2[b][1], e.y);
                add2(z2[b][0], xv[b].x);
                add2(z2[b][1], xv[b].y);
                float2 p0 = unpack2(z2[b][0]);   // {zi, zf}
                float2 p1 = unpack2(z2[b][1]);   // {zg, zo}
                float ig = sigf(p0.x);
                float fg = sigf(p0.y);
                float gg = fmaxf(p1.x, 0.f);
                float og = sigf(p1.y);
                cc[b] = fg * cc[b] + ig * gg;
                hv[b] = og * fmaxf(cc[b], 0.f);
                g_h1[((size_t)(t * BB + brow + b) << 7) + j] = hv[b];
            }
            *(ulonglong2*)(hn + (j << 3)) =
                make_ulonglong2(pack2(hv[0], hv[0]), pack2(hv[1], hv[1]));
            *(ulonglong2*)(hn + (j << 3) + 4) =
                make_ulonglong2(pack2(hv[2], hv[2]), pack2(hv[3], hv[3]));
        }
        __syncthreads();
        buf ^= 1;
    }
}

// ---------------------------------------------------------------------------
// Layer-2 recurrence (f32x2). 128 CTAs x 128 threads; (j in [0,64), ks in {0,1}).
// Per ks-half: 16 U rows in smem, 16 in registers.
// ---------------------------------------------------------------------------
#define REC2_SMEM ((32 * 256 + 2 * 64 * 8 + 64 * 20) * 4)  // 41984 B

__global__ __launch_bounds__(128, 1) void rec2_kernel()
{
    extern __shared__ float sm[];
    float* Us = sm;                  // [32][256]: s<16 -> k=s, s>=16 -> k=s+16
    float* hd = sm + 32 * 256;       // [2][64][8]
    float* ex = hd + 2 * 64 * 8;     // [64][20]

    const int tid  = threadIdx.x;
    const int j    = tid & 63;
    const int ks   = tid >> 6;
    const int brow = blockIdx.x << 2;

    for (int i = tid; i < 32 * 64; i += 128) {
        int s = i >> 6;
        int c = (i & 63) << 2;
        int krow = (s < 16) ? s : (s + 16);
        *(float4*)(Us + s * 256 + c) = *(const float4*)(g_Up2 + krow * 256 + c);
    }
    const int rbase = ks * 32 + 16;
    ulonglong2 uw[16];
#pragma unroll
    for (int r = 0; r < 16; r++)
        uw[r] = *(const ulonglong2*)(g_Up2 + (rbase + r) * 256 + (j << 2));
    for (int i = tid; i < 2 * 64 * 8; i += 128) hd[i] = 0.f;
    float cc[4] = {0.f, 0.f, 0.f, 0.f};
    __syncthreads();

    const float* up0 = Us + (ks * 16) * 256 + (j << 2);
    int buf = 0;
    for (int t = 0; t < TT; t++) {
        u64 z2[4][2];
#pragma unroll
        for (int b = 0; b < 4; b++) { z2[b][0] = 0ull; z2[b][1] = 0ull; }

        ulonglong2 xv[4];
        if (ks == 0) {
#pragma unroll
            for (int b = 0; b < 4; b++)
                xv[b] = *(const ulonglong2*)(g_xw2 + ((size_t)(t * BB + brow + b) << 8) + (j << 2));
        }
        const float* hb = hd + buf * 512;
        {
            const float* hp = hb + (ks * 32) * 8;
            const float* up = up0;
#pragma unroll 4
            for (int r = 0; r < 16; r++) {
                ulonglong2 hA = *(const ulonglong2*)(hp + (r << 3));
                ulonglong2 hB = *(const ulonglong2*)(hp + (r << 3) + 4);
                ulonglong2 uv = *(const ulonglong2*)(up);
                up += 256;
                fma2(z2[0][0], hA.x, uv.x); fma2(z2[0][1], hA.x, uv.y);
                fma2(z2[1][0], hA.y, uv.x); fma2(z2[1][1], hA.y, uv.y);
                fma2(z2[2][0], hB.x, uv.x); fma2(z2[2][1], hB.x, uv.y);
                fma2(z2[3][0], hB.y, uv.x); fma2(z2[3][1], hB.y, uv.y);
            }
        }
        {
            const float* hp = hb + rbase * 8;
#pragma unroll
            for (int r = 0; r < 16; r++) {
                ulonglong2 hA = *(const ulonglong2*)(hp + (r << 3));
                ulonglong2 hB = *(const ulonglong2*)(hp + (r << 3) + 4);
                fma2(z2[0][0], hA.x, uw[r].x); fma2(z2[0][1], hA.x, uw[r].y);
                fma2(z2[1][0], hA.y, uw[r].x); fma2(z2[1][1], hA.y, uw[r].y);
                fma2(z2[2][0], hB.x, uw[r].x); fma2(z2[2][1], hB.x, uw[r].y);
                fma2(z2[3][0], hB.y, uw[r].x); fma2(z2[3][1], hB.y, uw[r].y);
            }
        }
        if (ks) {
#pragma unroll
            for (int b = 0; b < 4; b++)
                *(ulonglong2*)(ex + j * 20 + (b << 2)) = make_ulonglong2(z2[b][0], z2[b][1]);
        }
        __syncthreads();
        if (ks == 0) {
            float* hn = hd + (buf ^ 1) * 512;
            float hv[4];
#pragma unroll
            for (int b = 0; b < 4; b++) {
                ulonglong2 e = *(const ulonglong2*)(ex + j * 20 + (b << 2));
                add2(z2[b][0], e.x);
                add2(z2[b][1], e.y);
                add2(z2[b][0], xv[b].x);
                add2(z2[b][1], xv[b].y);
                float2 p0 = unpack2(z2[b][0]);
                float2 p1 = unpack2(z2[b][1]);
                float ig = sigf(p0.x);
                float fg = sigf(p0.y);
                float gg = fmaxf(p1.x, 0.f);
                float og = sigf(p1.y);
                cc[b] = fg * cc[b] + ig * gg;
                hv[b] = og * fmaxf(cc[b], 0.f);
                if (t == TT - 1)
                    g_h2[((brow + b) << 6) + j] = hv[b];
            }
            *(ulonglong2*)(hn + (j << 3)) =
                make_ulonglong2(pack2(hv[0], hv[0]), pack2(hv[1], hv[1]));
            *(ulonglong2*)(hn + (j << 3) + 4) =
                make_ulonglong2(pack2(hv[2], hv[2]), pack2(hv[3], hv[3]));
        }
        __syncthreads();
        buf ^= 1;
    }
}

// ---------------------------------------------------------------------------
// Dense head: out[b] = (h2[b] @ Wd1 + bd1) @ Wd2 + bd2
// ---------------------------------------------------------------------------
__global__ void dense_kernel(const float* __restrict__ Wd1, const float* __restrict__ bd1,
                             const float* __restrict__ Wd2, const float* __restrict__ bd2,
                             float* __restrict__ out)
{
    int b = blockIdx.x * blockDim.x + threadIdx.x;
    if (b >= BB) return;
    float h[H2];
#pragma unroll
    for (int k = 0; k < H2; k++) h[k] = g_h2[(b << 6) + k];
    float acc = bd2[0];
    for (int d = 0; d < 25; d++) {
        float s = bd1[d];
#pragma unroll
        for (int k = 0; k < H2; k++) s += h[k] * Wd1[k * 25 + d];
        acc += s * Wd2[d];
    }
    out[b] = acc;
}

// ---------------------------------------------------------------------------
// Launch
// ---------------------------------------------------------------------------
extern "C" void kernel_launch(void* const* d_in, const int* in_sizes, int n_in,
                              void* d_out, int out_size)
{
    const float* x   = (const float*)d_in[0];
    const float* W1  = (const float*)d_in[1];
    const float* U1  = (const float*)d_in[2];
    const float* b1  = (const float*)d_in[3];
    const float* W2  = (const float*)d_in[4];
    const float* U2  = (const float*)d_in[5];
    const float* b2  = (const float*)d_in[6];
    const float* Wd1 = (const float*)d_in[7];
    const float* bd1 = (const float*)d_in[8];
    const float* Wd2 = (const float*)d_in[9];
    const float* bd2 = (const float*)d_in[10];
    float* out = (float*)d_out;

    cudaFuncSetAttribute(gemm_kernel, cudaFuncAttributeMaxDynamicSharedMemorySize, GEMM_SMEM);
    cudaFuncSetAttribute(rec1_kernel, cudaFuncAttributeMaxDynamicSharedMemorySize, REC1_SMEM);
    cudaFuncSetAttribute(rec2_kernel, cudaFuncAttributeMaxDynamicSharedMemorySize, REC2_SMEM);

    float *pWp1, *pbp1, *pWp2, *pbp2, *pxw1, *pxw2, *ph1;
    cudaGetSymbolAddress((void**)&pWp1, g_Wp1);
    cudaGetSymbolAddress((void**)&pbp1, g_bp1);
    cudaGetSymbolAddress((void**)&pWp2, g_Wp2);
    cudaGetSymbolAddress((void**)&pbp2, g_bp2);
    cudaGetSymbolAddress((void**)&pxw1, g_xw1);
    cudaGetSymbolAddress((void**)&pxw2, g_xw2);
    cudaGetSymbolAddress((void**)&ph1,  g_h1);

    // 1. permute weights into gate-interleaved layout
    prep_kernel<<<256, 256>>>(W1, U1, b1, W2, U2, b2);

    // 2. xW1: x[b][t][:] @ Wp1 -> g_xw1[t][b][:]
    gemm_kernel<<<dim3((TT * BB) / 128, G1 / 64), 256, GEMM_SMEM>>>(
        x, pWp1, pbp1, pxw1, FF, TT * FF, FF, G1);

    // 3. layer-1 recurrence -> g_h1[t][b][:]
    rec1_kernel<<<BB / 4, 256, REC1_SMEM>>>();

    // 4. xW2: h1[t][b][:] @ Wp2 -> g_xw2[t][b][:]
    gemm_kernel<<<dim3((TT * BB) / 128, G2 / 64), 256, GEMM_SMEM>>>(
        ph1, pWp2, pbp2, pxw2, BB * H1, H1, H1, G2);

    // 5. layer-2 recurrence -> g_h2[b][:]
    rec2_kernel<<<BB / 4, 128, REC2_SMEM>>>();

    // 6. dense head
    dense_kernel<<<2, 256>>>(Wd1, bd1, Wd2, bd2, out);
}

// round 3
// speedup vs baseline: 1.0311x; 1.0311x over previous
#include <cuda_runtime.h>
#include <cstddef>

// Problem constants
#define BB 512   // batch
#define TT 512   // timesteps
#define FF 64    // input features
#define H1 128   // layer1 hidden
#define G1 512   // 4*H1
#define H2 64    // layer2 hidden
#define G2 256   // 4*H2

typedef unsigned long long u64;

// ---------------------------------------------------------------------------
// Packed fp32x2 helpers (sm_103a): 2 IEEE fp32 FMAs per instruction.
// ---------------------------------------------------------------------------
__device__ __forceinline__ u64 pack2(float lo, float hi) {
    u64 r; asm("mov.b64 %0, {%1, %2};" : "=l"(r) : "f"(lo), "f"(hi)); return r;
}
__device__ __forceinline__ float2 unpack2(u64 v) {
    float2 f; asm("mov.b64 {%0, %1}, %2;" : "=f"(f.x), "=f"(f.y) : "l"(v)); return f;
}
__device__ __forceinline__ void fma2(u64& d, u64 a, u64 b) {
    asm("fma.rn.f32x2 %0, %1, %2, %0;" : "+l"(d) : "l"(a), "l"(b));
}
__device__ __forceinline__ void add2(u64& d, u64 a) {
    asm("add.rn.f32x2 %0, %0, %1;" : "+l"(d) : "l"(a));
}

// ---------------------------------------------------------------------------
// Device scratch
// ---------------------------------------------------------------------------
__device__ float g_Wp1[FF * G1];        // W1 permuted: [f][j*4+gate]
__device__ float g_bp1[G1];
__device__ float g_Up1[H1 * G1];        // U1 permuted: [k][j*4+gate]
__device__ float g_Wp2[H1 * G2];
__device__ float g_bp2[G2];
__device__ float g_Up2[H2 * G2];
__device__ float g_xw1[(size_t)TT * BB * G1];  // [t][b][j*4+gate]
__device__ float g_h1[(size_t)TT * BB * H1];   // [t][b][j]
__device__ float g_xw2[(size_t)TT * BB * G2];  // [t][b][j*4+gate]
__device__ float g_h2[BB * H2];                // final layer2 h

__device__ __forceinline__ float sigf(float x) {
    return __fdividef(1.0f, 1.0f + __expf(-x));
}

// ---------------------------------------------------------------------------
// Prep: permute weights so column n = j*4 + gate  (gate order i,f,g,o)
// ---------------------------------------------------------------------------
__global__ void prep_kernel(const float* __restrict__ W1, const float* __restrict__ U1,
                            const float* __restrict__ b1, const float* __restrict__ W2,
                            const float* __restrict__ U2, const float* __restrict__ b2)
{
    int i = blockIdx.x * blockDim.x + threadIdx.x;
    if (i < FF * G1) {
        int f = i >> 9, n = i & 511;
        int j = n >> 2, gi = n & 3;
        g_Wp1[i] = W1[f * G1 + gi * H1 + j];
    }
    if (i < G1) {
        int j = i >> 2, gi = i & 3;
        g_bp1[i] = b1[gi * H1 + j];
    }
    if (i < H1 * G1) {
        int k = i >> 9, n = i & 511;
        int j = n >> 2, gi = n & 3;
        g_Up1[i] = U1[k * G1 + gi * H1 + j];
    }
    if (i < H1 * G2) {
        int k = i >> 8, n = i & 255;
        int j = n >> 2, gi = n & 3;
        g_Wp2[i] = W2[k * G2 + gi * H2 + j];
    }
    if (i < G2) {
        int j = i >> 2, gi = i & 3;
        g_bp2[i] = b2[gi * H2 + j];
    }
    if (i < H2 * G2) {
        int k = i >> 8, n = i & 255;
        int j = n >> 2, gi = n & 3;
        g_Up2[i] = U2[k * G2 + gi * H2 + j];
    }
}

// ---------------------------------------------------------------------------
// FMA2-balanced GEMM:  C[m][n] = sum_k A_row(m)[k] * W[k][n] + bias[n]
// CTA tile 256(m) x 128(n), 256 threads, per-thread 16(m)x8(n) = 64 FMA2/k.
// A: k-major natural (lanes = m-pairs; ty-uniform address -> broadcast read).
// W: duplicated pairs in swizzled layout Wd[k][c][tx] so per-thread reads are
// contiguous 16B and conflict-free.
// ---------------------------------------------------------------------------
#define AS_LD 260                         // padded floats per k-row of A tile
#define GEMM_SMEM ((32 * AS_LD + 32 * 256) * 4)   // 66048 B

__global__ __launch_bounds__(256, 1) void gemm_kernel(
    const float* __restrict__ A, const float* __restrict__ W,
    const float* __restrict__ bias, float* __restrict__ C,
    int sT, int sB, int K, int N)
{
    extern __shared__ float sm[];
    float* As = sm;                  // [32][AS_LD]  k-major, m natural
    float* Wd = sm + 32 * AS_LD;     // [32][4][16][4]: dup pairs, swizzled by tx
    const int tid = threadIdx.x;
    const int tx = tid & 15;         // n group: covers n = tx*8 .. tx*8+7
    const int ty = tid >> 4;         // m group: covers m = ty*16 .. ty*16+15
    const int mt = blockIdx.x * 256;
    const int nt = blockIdx.y * 128;

    u64 acc[8][8];
#pragma unroll
    for (int p = 0; p < 8; p++)
#pragma unroll
        for (int q = 0; q < 8; q++) acc[p][q] = 0ull;

    const int am = tid;  // this thread loads A row m = tid (all 8 chunks contiguous)
    const int gm0 = mt + am;
    const int t0 = gm0 >> 9, b0 = gm0 & 511;
    const float* arow = A + (size_t)t0 * sT + (size_t)b0 * sB;

    for (int kt = 0; kt < K; kt += 32) {
        // ---- A tile: 256 rows x 32 k, transposed into smem (k-major) ----
#pragma unroll
        for (int kq = 0; kq < 8; kq++) {
            float4 v = *(const float4*)(arow + kt + (kq << 2));
            As[((kq << 2) + 0) * AS_LD + am] = v.x;
            As[((kq << 2) + 1) * AS_LD + am] = v.y;
            As[((kq << 2) + 2) * AS_LD + am] = v.z;
            As[((kq << 2) + 3) * AS_LD + am] = v.w;
        }
        // ---- W tile: 32 k x 128 n, duplicated + swizzled ----
        {
            int txw = tid & 15;
            int c   = (tid >> 4) & 3;
            int kb  = tid >> 6;          // 0..3
#pragma unroll
            for (int i = 0; i < 8; i++) {
                int k = kb + (i << 2);   // 0..31
                float2 w2 = *(const float2*)(W + (size_t)(kt + k) * N + nt + (txw << 3) + (c << 1));
                *(float4*)(Wd + (k << 8) + (c << 6) + (txw << 2)) =
                    make_float4(w2.x, w2.x, w2.y, w2.y);
            }
        }
        __syncthreads();
        // ---- compute ----
#pragma unroll 4
        for (int k = 0; k < 32; k++) {
            const float* ar = As + k * AS_LD + (ty << 4);
            ulonglong2 a01 = *(const ulonglong2*)(ar);
            ulonglong2 a23 = *(const ulonglong2*)(ar + 4);
            ulonglong2 a45 = *(const ulonglong2*)(ar + 8);
            ulonglong2 a67 = *(const ulonglong2*)(ar + 12);
            const float* wr = Wd + (k << 8) + (tx << 2);
            ulonglong2 w01 = *(const ulonglong2*)(wr);
            ulonglong2 w23 = *(const ulonglong2*)(wr + 64);
            ulonglong2 w45 = *(const ulonglong2*)(wr + 128);
            ulonglong2 w67 = *(const ulonglong2*)(wr + 192);
            u64 av[8] = {a01.x, a01.y, a23.x, a23.y, a45.x, a45.y, a67.x, a67.y};
            u64 wv[8] = {w01.x, w01.y, w23.x, w23.y, w45.x, w45.y, w67.x, w67.y};
#pragma unroll
            for (int p = 0; p < 8; p++)
#pragma unroll
                for (int q = 0; q < 8; q++) fma2(acc[p][q], av[p], wv[q]);
        }
        __syncthreads();
    }

    // ---- epilogue: bias + store ----
    u64 bd[8];
#pragma unroll
    for (int q = 0; q < 8; q++) {
        float bv = bias[nt + (tx << 3) + q];
        bd[q] = pack2(bv, bv);
    }
#pragma unroll
    for (int p = 0; p < 8; p++) {
        float2 f[8];
#pragma unroll
        for (int q = 0; q < 8; q++) {
            add2(acc[p][q], bd[q]);
            f[q] = unpack2(acc[p][q]);
        }
        int m0 = mt + (ty << 4) + (p << 1);
        float* c0 = C + (size_t)m0 * N + nt + (tx << 3);
        float* c1 = c0 + N;
        *(float4*)(c0)     = make_float4(f[0].x, f[1].x, f[2].x, f[3].x);
        *(float4*)(c0 + 4) = make_float4(f[4].x, f[5].x, f[6].x, f[7].x);
        *(float4*)(c1)     = make_float4(f[0].y, f[1].y, f[2].y, f[3].y);
        *(float4*)(c1 + 4) = make_float4(f[4].y, f[5].y, f[6].y, f[7].y);
    }
}

// ---------------------------------------------------------------------------
// Layer-1 recurrence (f32x2). 128 CTAs x 256 threads; CTA owns 4 batch rows.
// thread = (j in [0,128), ks in {0,1}); ks splits the K=128 reduction.
// Per ks-half: 32 U rows in smem, 32 in registers. h kept in smem as
// duplicated pairs {h,h} (warp-uniform address -> broadcast read).
// ---------------------------------------------------------------------------
#define REC1_SMEM ((64 * 512 + 2 * 128 * 8 + 128 * 20) * 4)  // 149504 B

__global__ __launch_bounds__(256, 1) void rec1_kernel()
{
    extern __shared__ float sm[];
    float* Us = sm;                  // [64][512]: s<32 -> k=s (ks0), s>=32 -> k=s+32 (ks1)
    float* hd = sm + 64 * 512;       // [2][128][8]: per k-row {h0,h0,h1,h1,h2,h2,h3,h3}
    float* ex = hd + 2 * 128 * 8;    // [128][20]: ks=1 partials (padded stride)

    const int tid  = threadIdx.x;
    const int j    = tid & 127;
    const int ks   = tid >> 7;
    const int brow = blockIdx.x << 2;

    // cooperative load of smem-resident U rows
    for (int i = tid; i < 64 * 128; i += 256) {
        int s = i >> 7;
        int c = (i & 127) << 2;
        int krow = (s < 32) ? s : (s + 32);
        *(float4*)(Us + s * 512 + c) = *(const float4*)(g_Up1 + krow * 512 + c);
    }
    // register-resident U rows (gate pairs)
    const int rbase = ks * 64 + 32;
    ulonglong2 uw[32];
#pragma unroll
    for (int r = 0; r < 32; r++)
        uw[r] = *(const ulonglong2*)(g_Up1 + (rbase + r) * 512 + (j << 2));
    for (int i = tid; i < 2 * 128 * 8; i += 256) hd[i] = 0.f;  // h0 = 0
    float cc[4] = {0.f, 0.f, 0.f, 0.f};
    __syncthreads();

    const float* up0 = Us + (ks * 32) * 512 + (j << 2);
    int buf = 0;
    for (int t = 0; t < TT; t++) {
        u64 z2[4][2];
#pragma unroll
        for (int b = 0; b < 4; b++) { z2[b][0] = 0ull; z2[b][1] = 0ull; }

        ulonglong2 xv[4];
        if (ks == 0) {  // issue early; consumed after the FMA loop
#pragma unroll
            for (int b = 0; b < 4; b++)
                xv[b] = *(const ulonglong2*)(g_xw1 + ((size_t)(t * BB + brow + b) << 9) + (j << 2));
        }

        const float* hb = hd + buf * 1024;
        {   // smem U rows: k = ks*64 + [0,32)
            const float* hp = hb + (ks * 64) * 8;
            const float* up = up0;
#pragma unroll 4
            for (int r = 0; r < 32; r++) {
                ulonglong2 hA = *(const ulonglong2*)(hp + (r << 3));      // {h0,h0},{h1,h1}
                ulonglong2 hB = *(const ulonglong2*)(hp + (r << 3) + 4);  // {h2,h2},{h3,h3}
                ulonglong2 uv = *(const ulonglong2*)(up);
                up += 512;
                fma2(z2[0][0], hA.x, uv.x); fma2(z2[0][1], hA.x, uv.y);
                fma2(z2[1][0], hA.y, uv.x); fma2(z2[1][1], hA.y, uv.y);
                fma2(z2[2][0], hB.x, uv.x); fma2(z2[2][1], hB.x, uv.y);
                fma2(z2[3][0], hB.y, uv.x); fma2(z2[3][1], hB.y, uv.y);
            }
        }
        {   // register U rows: k = ks*64 + [32,64)
            const float* hp = hb + rbase * 8;
#pragma unroll
            for (int r = 0; r < 32; r++) {
                ulonglong2 hA = *(const ulonglong2*)(hp + (r << 3));
                ulonglong2 hB = *(const ulonglong2*)(hp + (r << 3) + 4);
                fma2(z2[0][0], hA.x, uw[r].x); fma2(z2[0][1], hA.x, uw[r].y);
                fma2(z2[1][0], hA.y, uw[r].x); fma2(z2[1][1], hA.y, uw[r].y);
                fma2(z2[2][0], hB.x, uw[r].x); fma2(z2[2][1], hB.x, uw[r].y);
                fma2(z2[3][0], hB.y, uw[r].x); fma2(z2[3][1], hB.y, uw[r].y);
            }
        }
        if (ks) {
#pragma unroll
            for (int b = 0; b < 4; b++)
                *(ulonglong2*)(ex + j * 20 + (b << 2)) = make_ulonglong2(z2[b][0], z2[b][1]);
        }
        __syncthreads();
        if (ks == 0) {
            float* hn = hd + (buf ^ 1) * 1024;
            float hv[4];
#pragma unroll
            for (int b = 0; b < 4; b++) {
                ulonglong2 e = *(const ulonglong2*)(ex + j * 20 + (b << 2));
                add2(z2[b][0], e.x);
                add2(z2[b][1], e.y);
                add2(z2[b][0], xv[b].x);
                add2(z2[b][1], xv[b].y);
                float2 p0 = unpack2(z2[b][0]);   // {zi, zf}
                float2 p1 = unpack2(z2[b][1]);   // {zg, zo}
                float ig = sigf(p0.x);
                float fg = sigf(p0.y);
                float gg = fmaxf(p1.x, 0.f);
                float og = sigf(p1.y);
                cc[b] = fg * cc[b] + ig * gg;
                hv[b] = og * fmaxf(cc[b], 0.f);
                g_h1[((size_t)(t * BB + brow + b) << 7) + j] = hv[b];
            }
            *(ulonglong2*)(hn + (j << 3)) =
                make_ulonglong2(pack2(hv[0], hv[0]), pack2(hv[1], hv[1]));
            *(ulonglong2*)(hn + (j << 3) + 4) =
                make_ulonglong2(pack2(hv[2], hv[2]), pack2(hv[3], hv[3]));
        }
        __syncthreads();
        buf ^= 1;
    }
}

// ---------------------------------------------------------------------------
// Layer-2 recurrence (f32x2). 128 CTAs x 128 threads; (j in [0,64), ks in {0,1}).
// ---------------------------------------------------------------------------
#define REC2_SMEM ((32 * 256 + 2 * 64 * 8 + 64 * 20) * 4)  // 41984 B

__global__ __launch_bounds__(128, 1) void rec2_kernel()
{
    extern __shared__ float sm[];
    float* Us = sm;                  // [32][256]: s<16 -> k=s, s>=16 -> k=s+16
    float* hd = sm + 32 * 256;       // [2][64][8]
    float* ex = hd + 2 * 64 * 8;     // [64][20]

    const int tid  = threadIdx.x;
    const int j    = tid & 63;
    const int ks   = tid >> 6;
    const int brow = blockIdx.x << 2;

    for (int i = tid; i < 32 * 64; i += 128) {
        int s = i >> 6;
        int c = (i & 63) << 2;
        int krow = (s < 16) ? s : (s + 16);
        *(float4*)(Us + s * 256 + c) = *(const float4*)(g_Up2 + krow * 256 + c);
    }
    const int rbase = ks * 32 + 16;
    ulonglong2 uw[16];
#pragma unroll
    for (int r = 0; r < 16; r++)
        uw[r] = *(const ulonglong2*)(g_Up2 + (rbase + r) * 256 + (j << 2));
    for (int i = tid; i < 2 * 64 * 8; i += 128) hd[i] = 0.f;
    float cc[4] = {0.f, 0.f, 0.f, 0.f};
    __syncthreads();

    const float* up0 = Us + (ks * 16) * 256 + (j << 2);
    int buf = 0;
    for (int t = 0; t < TT; t++) {
        u64 z2[4][2];
#pragma unroll
        for (int b = 0; b < 4; b++) { z2[b][0] = 0ull; z2[b][1] = 0ull; }

        ulonglong2 xv[4];
        if (ks == 0) {
#pragma unroll
            for (int b = 0; b < 4; b++)
                xv[b] = *(const ulonglong2*)(g_xw2 + ((size_t)(t * BB + brow + b) << 8) + (j << 2));
        }
        const float* hb = hd + buf * 512;
        {
            const float* hp = hb + (ks * 32) * 8;
            const float* up = up0;
#pragma unroll 4
            for (int r = 0; r < 16; r++) {
                ulonglong2 hA = *(const ulonglong2*)(hp + (r << 3));
                ulonglong2 hB = *(const ulonglong2*)(hp + (r << 3) + 4);
                ulonglong2 uv = *(const ulonglong2*)(up);
                up += 256;
                fma2(z2[0][0], hA.x, uv.x); fma2(z2[0][1], hA.x, uv.y);
                fma2(z2[1][0], hA.y, uv.x); fma2(z2[1][1], hA.y, uv.y);
                fma2(z2[2][0], hB.x, uv.x); fma2(z2[2][1], hB.x, uv.y);
                fma2(z2[3][0], hB.y, uv.x); fma2(z2[3][1], hB.y, uv.y);
            }
        }
        {
            const float* hp = hb + rbase * 8;
#pragma unroll
            for (int r = 0; r < 16; r++) {
                ulonglong2 hA = *(const ulonglong2*)(hp + (r << 3));
                ulonglong2 hB = *(const ulonglong2*)(hp + (r << 3) + 4);
                fma2(z2[0][0], hA.x, uw[r].x); fma2(z2[0][1], hA.x, uw[r].y);
                fma2(z2[1][0], hA.y, uw[r].x); fma2(z2[1][1], hA.y, uw[r].y);
                fma2(z2[2][0], hB.x, uw[r].x); fma2(z2[2][1], hB.x, uw[r].y);
                fma2(z2[3][0], hB.y, uw[r].x); fma2(z2[3][1], hB.y, uw[r].y);
            }
        }
        if (ks) {
#pragma unroll
            for (int b = 0; b < 4; b++)
                *(ulonglong2*)(ex + j * 20 + (b << 2)) = make_ulonglong2(z2[b][0], z2[b][1]);
        }
        __syncthreads();
        if (ks == 0) {
            float* hn = hd + (buf ^ 1) * 512;
            float hv[4];
#pragma unroll
            for (int b = 0; b < 4; b++) {
                ulonglong2 e = *(const ulonglong2*)(ex + j * 20 + (b << 2));
                add2(z2[b][0], e.x);
                add2(z2[b][1], e.y);
                add2(z2[b][0], xv[b].x);
                add2(z2[b][1], xv[b].y);
                float2 p0 = unpack2(z2[b][0]);
                float2 p1 = unpack2(z2[b][1]);
                float ig = sigf(p0.x);
                float fg = sigf(p0.y);
                float gg = fmaxf(p1.x, 0.f);
                float og = sigf(p1.y);
                cc[b] = fg * cc[b] + ig * gg;
                hv[b] = og * fmaxf(cc[b], 0.f);
                if (t == TT - 1)
                    g_h2[((brow + b) << 6) + j] = hv[b];
            }
            *(ulonglong2*)(hn + (j << 3)) =
                make_ulonglong2(pack2(hv[0], hv[0]), pack2(hv[1], hv[1]));
            *(ulonglong2*)(hn + (j << 3) + 4) =
                make_ulonglong2(pack2(hv[2], hv[2]), pack2(hv[3], hv[3]));
        }
        __syncthreads();
        buf ^= 1;
    }
}

// ---------------------------------------------------------------------------
// Dense head: out[b] = (h2[b] @ Wd1 + bd1) @ Wd2 + bd2
// ---------------------------------------------------------------------------
__global__ void dense_kernel(const float* __restrict__ Wd1, const float* __restrict__ bd1,
                             const float* __restrict__ Wd2, const float* __restrict__ bd2,
                             float* __restrict__ out)
{
    int b = blockIdx.x * blockDim.x + threadIdx.x;
    if (b >= BB) return;
    float h[H2];
#pragma unroll
    for (int k = 0; k < H2; k++) h[k] = g_h2[(b << 6) + k];
    float acc = bd2[0];
    for (int d = 0; d < 25; d++) {
        float s = bd1[d];
#pragma unroll
        for (int k = 0; k < H2; k++) s += h[k] * Wd1[k * 25 + d];
        acc += s * Wd2[d];
    }
    out[b] = acc;
}

// ---------------------------------------------------------------------------
// Launch
// ---------------------------------------------------------------------------
extern "C" void kernel_launch(void* const* d_in, const int* in_sizes, int n_in,
                              void* d_out, int out_size)
{
    const float* x   = (const float*)d_in[0];
    const float* W1  = (const float*)d_in[1];
    const float* U1  = (const float*)d_in[2];
    const float* b1  = (const float*)d_in[3];
    const float* W2  = (const float*)d_in[4];
    const float* U2  = (const float*)d_in[5];
    const float* b2  = (const float*)d_in[6];
    const float* Wd1 = (const float*)d_in[7];
    const float* bd1 = (const float*)d_in[8];
    const float* Wd2 = (const float*)d_in[9];
    const float* bd2 = (const float*)d_in[10];
    float* out = (float*)d_out;

    cudaFuncSetAttribute(gemm_kernel, cudaFuncAttributeMaxDynamicSharedMemorySize, GEMM_SMEM);
    cudaFuncSetAttribute(rec1_kernel, cudaFuncAttributeMaxDynamicSharedMemorySize, REC1_SMEM);
    cudaFuncSetAttribute(rec2_kernel, cudaFuncAttributeMaxDynamicSharedMemorySize, REC2_SMEM);

    float *pWp1, *pbp1, *pWp2, *pbp2, *pxw1, *pxw2, *ph1;
    cudaGetSymbolAddress((void**)&pWp1, g_Wp1);
    cudaGetSymbolAddress((void**)&pbp1, g_bp1);
    cudaGetSymbolAddress((void**)&pWp2, g_Wp2);
    cudaGetSymbolAddress((void**)&pbp2, g_bp2);
    cudaGetSymbolAddress((void**)&pxw1, g_xw1);
    cudaGetSymbolAddress((void**)&pxw2, g_xw2);
    cudaGetSymbolAddress((void**)&ph1,  g_h1);

    // 1. permute weights into gate-interleaved layout
    prep_kernel<<<256, 256>>>(W1, U1, b1, W2, U2, b2);

    // 2. xW1: x[b][t][:] @ Wp1 -> g_xw1[t][b][:]
    gemm_kernel<<<dim3((TT * BB) / 256, G1 / 128), 256, GEMM_SMEM>>>(
        x, pWp1, pbp1, pxw1, FF, TT * FF, FF, G1);

    // 3. layer-1 recurrence -> g_h1[t][b][:]
    rec1_kernel<<<BB / 4, 256, REC1_SMEM>>>();

    // 4. xW2: h1[t][b][:] @ Wp2 -> g_xw2[t][b][:]
    gemm_kernel<<<dim3((TT * BB) / 256, G2 / 128), 256, GEMM_SMEM>>>(
        ph1, pWp2, pbp2, pxw2, BB * H1, H1, H1, G2);

    // 5. layer-2 recurrence -> g_h2[b][:]
    rec2_kernel<<<BB / 4, 128, REC2_SMEM>>>();

    // 6. dense head
    dense_kernel<<<2, 256>>>(Wd1, bd1, Wd2, bd2, out);
}

// round 4
// speedup vs baseline: 1.0915x; 1.0586x over previous
#include <cuda_runtime.h>
#include <cstddef>

// Problem constants
#define BB 512   // batch
#define TT 512   // timesteps
#define FF 64    // input features
#define H1 128   // layer1 hidden
#define G1 512   // 4*H1
#define H2 64    // layer2 hidden
#define G2 256   // 4*H2

typedef unsigned long long u64;

// ---------------------------------------------------------------------------
// Packed fp32x2 helpers (sm_103a): 2 IEEE fp32 FMAs per instruction.
// ---------------------------------------------------------------------------
__device__ __forceinline__ u64 pack2(float lo, float hi) {
    u64 r; asm("mov.b64 %0, {%1, %2};" : "=l"(r) : "f"(lo), "f"(hi)); return r;
}
__device__ __forceinline__ float2 unpack2(u64 v) {
    float2 f; asm("mov.b64 {%0, %1}, %2;" : "=f"(f.x), "=f"(f.y) : "l"(v)); return f;
}
__device__ __forceinline__ void fma2(u64& d, u64 a, u64 b) {
    asm("fma.rn.f32x2 %0, %1, %2, %0;" : "+l"(d) : "l"(a), "l"(b));
}
__device__ __forceinline__ void add2(u64& d, u64 a) {
    asm("add.rn.f32x2 %0, %0, %1;" : "+l"(d) : "l"(a));
}

// ---------------------------------------------------------------------------
// Device scratch
// ---------------------------------------------------------------------------
__device__ float g_Wp1[FF * G1];        // W1 permuted: [f][j*4+gate]
__device__ float g_bp1[G1];
__device__ float g_Up1[H1 * G1];        // U1 permuted: [k][j*4+gate]
__device__ float g_Wp2[H1 * G2];
__device__ float g_bp2[G2];
__device__ float g_Up2[H2 * G2];
__device__ float g_xw1[(size_t)TT * BB * G1];  // [t][b][j*4+gate]
__device__ float g_h1[(size_t)TT * BB * H1];   // [t][b][j]
__device__ float g_xw2[(size_t)TT * BB * G2];  // [t][b][j*4+gate]
__device__ float g_h2[BB * H2];                // final layer2 h

__device__ __forceinline__ float sigf(float x) {
    return __fdividef(1.0f, 1.0f + __expf(-x));
}

// ---------------------------------------------------------------------------
// Prep: permute weights so column n = j*4 + gate  (gate order i,f,g,o)
// ---------------------------------------------------------------------------
__global__ void prep_kernel(const float* __restrict__ W1, const float* __restrict__ U1,
                            const float* __restrict__ b1, const float* __restrict__ W2,
                            const float* __restrict__ U2, const float* __restrict__ b2)
{
    int i = blockIdx.x * blockDim.x + threadIdx.x;
    if (i < FF * G1) {
        int f = i >> 9, n = i & 511;
        int j = n >> 2, gi = n & 3;
        g_Wp1[i] = W1[f * G1 + gi * H1 + j];
    }
    if (i < G1) {
        int j = i >> 2, gi = i & 3;
        g_bp1[i] = b1[gi * H1 + j];
    }
    if (i < H1 * G1) {
        int k = i >> 9, n = i & 511;
        int j = n >> 2, gi = n & 3;
        g_Up1[i] = U1[k * G1 + gi * H1 + j];
    }
    if (i < H1 * G2) {
        int k = i >> 8, n = i & 255;
        int j = n >> 2, gi = n & 3;
        g_Wp2[i] = W2[k * G2 + gi * H2 + j];
    }
    if (i < G2) {
        int j = i >> 2, gi = i & 3;
        g_bp2[i] = b2[gi * H2 + j];
    }
    if (i < H2 * G2) {
        int k = i >> 8, n = i & 255;
        int j = n >> 2, gi = n & 3;
        g_Up2[i] = U2[k * G2 + gi * H2 + j];
    }
}

// ---------------------------------------------------------------------------
// FMA2 GEMM, occupancy-2:  C[m][n] = sum_k A_row(m)[k] * W[k][n] + bias[n]
// CTA tile 128(m) x 128(n), 256 threads, per-thread 8(m)x8(n) = 32 FMA2/k.
// 2 CTAs / SM (regs ~105, smem 49.7KB) -> 16 warps for issue hiding.
// A: k-major natural (m-pairs in LDS.128; 2 addrs/warp -> near-broadcast).
// W: duplicated pairs, swizzled Wd[k][c][tx] so reads are 16B conflict-free.
// ---------------------------------------------------------------------------
#define AS_LD 132                        // padded floats per k-row of A tile
#define GEMM_SMEM ((32 * AS_LD + 32 * 256) * 4)   // 49664 B

__global__ __launch_bounds__(256, 2) void gemm_kernel(
    const float* __restrict__ A, const float* __restrict__ W,
    const float* __restrict__ bias, float* __restrict__ C,
    int sT, int sB, int K, int N)
{
    extern __shared__ float sm[];
    float* As = sm;                  // [32][AS_LD]  k-major, m natural
    float* Wd = sm + 32 * AS_LD;     // [32][4][16][4]: dup pairs, swizzled by tx
    const int tid = threadIdx.x;
    const int tx = tid & 15;         // n group: n = tx*8 .. tx*8+7
    const int ty = tid >> 4;         // m group: m = ty*8 .. ty*8+7
    const int mt = blockIdx.x * 128;
    const int nt = blockIdx.y * 128;

    u64 acc[4][8];
#pragma unroll
    for (int p = 0; p < 4; p++)
#pragma unroll
        for (int q = 0; q < 8; q++) acc[p][q] = 0ull;

    // A loader: thread handles row am = tid&127, k-span kc*16..kc*16+15
    const int am = tid & 127;
    const int kc = tid >> 7;
    const int gm0 = mt + am;
    const int t0 = gm0 >> 9, b0 = gm0 & 511;
    const float* arow = A + (size_t)t0 * sT + (size_t)b0 * sB + (kc << 4);

    for (int kt = 0; kt < K; kt += 32) {
        // ---- A tile: 128 rows x 32 k, transposed into smem (k-major) ----
#pragma unroll
        for (int kq = 0; kq < 4; kq++) {
            float4 v = *(const float4*)(arow + kt + (kq << 2));
            int kk = (kc << 4) + (kq << 2);
            As[(kk + 0) * AS_LD + am] = v.x;
            As[(kk + 1) * AS_LD + am] = v.y;
            As[(kk + 2) * AS_LD + am] = v.z;
            As[(kk + 3) * AS_LD + am] = v.w;
        }
        // ---- W tile: 32 k x 128 n, duplicated + swizzled ----
        {
            int txw = tid & 15;
            int c   = (tid >> 4) & 3;
            int kb  = tid >> 6;          // 0..3
#pragma unroll
            for (int i = 0; i < 8; i++) {
                int k = kb + (i << 2);   // 0..31
                float2 w2 = *(const float2*)(W + (size_t)(kt + k) * N + nt + (txw << 3) + (c << 1));
                *(float4*)(Wd + (k << 8) + (c << 6) + (txw << 2)) =
                    make_float4(w2.x, w2.x, w2.y, w2.y);
            }
        }
        __syncthreads();
        // ---- compute ----
#pragma unroll 4
        for (int k = 0; k < 32; k++) {
            const float* ar = As + k * AS_LD + (ty << 3);
            ulonglong2 a01 = *(const ulonglong2*)(ar);        // m-pairs (0,1),(2,3)
            ulonglong2 a23 = *(const ulonglong2*)(ar + 4);    // m-pairs (4,5),(6,7)
            const float* wr = Wd + (k << 8) + (tx << 2);
            ulonglong2 w01 = *(const ulonglong2*)(wr);
            ulonglong2 w23 = *(const ulonglong2*)(wr + 64);
            ulonglong2 w45 = *(const ulonglong2*)(wr + 128);
            ulonglong2 w67 = *(const ulonglong2*)(wr + 192);
            u64 av[4] = {a01.x, a01.y, a23.x, a23.y};
            u64 wv[8] = {w01.x, w01.y, w23.x, w23.y, w45.x, w45.y, w67.x, w67.y};
#pragma unroll
            for (int p = 0; p < 4; p++)
#pragma unroll
                for (int q = 0; q < 8; q++) fma2(acc[p][q], av[p], wv[q]);
        }
        __syncthreads();
    }

    // ---- epilogue: bias + store ----
    u64 bd[8];
#pragma unroll
    for (int q = 0; q < 8; q++) {
        float bv = bias[nt + (tx << 3) + q];
        bd[q] = pack2(bv, bv);
    }
#pragma unroll
    for (int p = 0; p < 4; p++) {
        float2 f[8];
#pragma unroll
        for (int q = 0; q < 8; q++) {
            add2(acc[p][q], bd[q]);
            f[q] = unpack2(acc[p][q]);
        }
        int m0 = mt + (ty << 3) + (p << 1);
        float* c0 = C + (size_t)m0 * N + nt + (tx << 3);
        float* c1 = c0 + N;
        *(float4*)(c0)     = make_float4(f[0].x, f[1].x, f[2].x, f[3].x);
        *(float4*)(c0 + 4) = make_float4(f[4].x, f[5].x, f[6].x, f[7].x);
        *(float4*)(c1)     = make_float4(f[0].y, f[1].y, f[2].y, f[3].y);
        *(float4*)(c1 + 4) = make_float4(f[4].y, f[5].y, f[6].y, f[7].y);
    }
}

// ---------------------------------------------------------------------------
// Layer-1 recurrence (f32x2). 128 CTAs x 256 threads; CTA owns 4 batch rows.
// thread = (j in [0,128), ks in {0,1}); ks splits the K=128 reduction.
// Per ks-half: 32 U rows in smem, 32 in registers. h kept in smem as
// duplicated pairs {h,h} (warp-uniform address -> broadcast read).
// ---------------------------------------------------------------------------
#define REC1_SMEM ((64 * 512 + 2 * 128 * 8 + 128 * 20) * 4)  // 149504 B

__global__ __launch_bounds__(256, 1) void rec1_kernel()
{
    extern __shared__ float sm[];
    float* Us = sm;                  // [64][512]: s<32 -> k=s (ks0), s>=32 -> k=s+32 (ks1)
    float* hd = sm + 64 * 512;       // [2][128][8]: per k-row {h0,h0,h1,h1,h2,h2,h3,h3}
    float* ex = hd + 2 * 128 * 8;    // [128][20]: ks=1 partials (padded stride)

    const int tid  = threadIdx.x;
    const int j    = tid & 127;
    const int ks   = tid >> 7;
    const int brow = blockIdx.x << 2;

    // cooperative load of smem-resident U rows
    for (int i = tid; i < 64 * 128; i += 256) {
        int s = i >> 7;
        int c = (i & 127) << 2;
        int krow = (s < 32) ? s : (s + 32);
        *(float4*)(Us + s * 512 + c) = *(const float4*)(g_Up1 + krow * 512 + c);
    }
    // register-resident U rows (gate pairs)
    const int rbase = ks * 64 + 32;
    ulonglong2 uw[32];
#pragma unroll
    for (int r = 0; r < 32; r++)
        uw[r] = *(const ulonglong2*)(g_Up1 + (rbase + r) * 512 + (j << 2));
    for (int i = tid; i < 2 * 128 * 8; i += 256) hd[i] = 0.f;  // h0 = 0
    float cc[4] = {0.f, 0.f, 0.f, 0.f};
    __syncthreads();

    const float* up0 = Us + (ks * 32) * 512 + (j << 2);
    int buf = 0;
    for (int t = 0; t < TT; t++) {
        u64 z2[4][2];
#pragma unroll
        for (int b = 0; b < 4; b++) { z2[b][0] = 0ull; z2[b][1] = 0ull; }

        ulonglong2 xv[4];
        if (ks == 0) {  // issue early; consumed after the FMA loop
#pragma unroll
            for (int b = 0; b < 4; b++)
                xv[b] = *(const ulonglong2*)(g_xw1 + ((size_t)(t * BB + brow + b) << 9) + (j << 2));
        }

        const float* hb = hd + buf * 1024;
        {   // smem U rows: k = ks*64 + [0,32)
            const float* hp = hb + (ks * 64) * 8;
            const float* up = up0;
#pragma unroll 4
            for (int r = 0; r < 32; r++) {
                ulonglong2 hA = *(const ulonglong2*)(hp + (r << 3));      // {h0,h0},{h1,h1}
                ulonglong2 hB = *(const ulonglong2*)(hp + (r << 3) + 4);  // {h2,h2},{h3,h3}
                ulonglong2 uv = *(const ulonglong2*)(up);
                up += 512;
                fma2(z2[0][0], hA.x, uv.x); fma2(z2[0][1], hA.x, uv.y);
                fma2(z2[1][0], hA.y, uv.x); fma2(z2[1][1], hA.y, uv.y);
                fma2(z2[2][0], hB.x, uv.x); fma2(z2[2][1], hB.x, uv.y);
                fma2(z2[3][0], hB.y, uv.x); fma2(z2[3][1], hB.y, uv.y);
            }
        }
        {   // register U rows: k = ks*64 + [32,64)
            const float* hp = hb + rbase * 8;
#pragma unroll
            for (int r = 0; r < 32; r++) {
                ulonglong2 hA = *(const ulonglong2*)(hp + (r << 3));
                ulonglong2 hB = *(const ulonglong2*)(hp + (r << 3) + 4);
                fma2(z2[0][0], hA.x, uw[r].x); fma2(z2[0][1], hA.x, uw[r].y);
                fma2(z2[1][0], hA.y, uw[r].x); fma2(z2[1][1], hA.y, uw[r].y);
                fma2(z2[2][0], hB.x, uw[r].x); fma2(z2[2][1], hB.x, uw[r].y);
                fma2(z2[3][0], hB.y, uw[r].x); fma2(z2[3][1], hB.y, uw[r].y);
            }
        }
        if (ks) {
#pragma unroll
            for (int b = 0; b < 4; b++)
                *(ulonglong2*)(ex + j * 20 + (b << 2)) = make_ulonglong2(z2[b][0], z2[b][1]);
        }
        __syncthreads();
        if (ks == 0) {
            float* hn = hd + (buf ^ 1) * 1024;
            float hv[4];
#pragma unroll
            for (int b = 0; b < 4; b++) {
                ulonglong2 e = *(const ulonglong2*)(ex + j * 20 + (b << 2));
                add2(z2[b][0], e.x);
                add2(z2[b][1], e.y);
                add2(z2[b][0], xv[b].x);
                add2(z2[b][1], xv[b].y);
                float2 p0 = unpack2(z2[b][0]);   // {zi, zf}
                float2 p1 = unpack2(z2[b][1]);   // {zg, zo}
                float ig = sigf(p0.x);
                float fg = sigf(p0.y);
                float gg = fmaxf(p1.x, 0.f);
                float og = sigf(p1.y);
                cc[b] = fg * cc[b] + ig * gg;
                hv[b] = og * fmaxf(cc[b], 0.f);
                g_h1[((size_t)(t * BB + brow + b) << 7) + j] = hv[b];
            }
            *(ulonglong2*)(hn + (j << 3)) =
                make_ulonglong2(pack2(hv[0], hv[0]), pack2(hv[1], hv[1]));
            *(ulonglong2*)(hn + (j << 3) + 4) =
                make_ulonglong2(pack2(hv[2], hv[2]), pack2(hv[3], hv[3]));
        }
        __syncthreads();
        buf ^= 1;
    }
}

// ---------------------------------------------------------------------------
// Layer-2 recurrence (f32x2), 4-way k-split. 128 CTAs x 256 threads.
// thread = (j in [0,64), ks in {0,1,2,3}); ks covers k rows [ks*16, ks*16+16):
// first 8 rows from smem, last 8 from registers. Quarters 1..3 write partials
// to ex; quarter 0 combines + applies gates.
// ---------------------------------------------------------------------------
#define REC2_SMEM ((32 * 256 + 2 * 64 * 8 + 3 * 64 * 20) * 4)  // 52480 B

__global__ __launch_bounds__(256, 1) void rec2_kernel()
{
    extern __shared__ float sm[];
    float* Us = sm;                  // [32][256]: s = q*8+r  <->  krow = q*16+r
    float* hd = sm + 32 * 256;       // [2][64][8]
    float* ex = hd + 2 * 64 * 8;     // [3][64][20]

    const int tid  = threadIdx.x;
    const int j    = tid & 63;
    const int ks   = tid >> 6;       // 0..3
    const int brow = blockIdx.x << 2;

    // cooperative load of smem-resident U rows (8 per quarter)
    for (int i = tid; i < 32 * 64; i += 256) {
        int s = i >> 6;
        int c = (i & 63) << 2;
        int krow = ((s >> 3) << 4) + (s & 7);
        *(float4*)(Us + s * 256 + c) = *(const float4*)(g_Up2 + krow * 256 + c);
    }
    // register rows: krow = ks*16 + 8 + r
    const int rbase = (ks << 4) + 8;
    ulonglong2 uw[8];
#pragma unroll
    for (int r = 0; r < 8; r++)
        uw[r] = *(const ulonglong2*)(g_Up2 + (rbase + r) * 256 + (j << 2));
    for (int i = tid; i < 2 * 64 * 8; i += 256) hd[i] = 0.f;
    float cc[4] = {0.f, 0.f, 0.f, 0.f};
    __syncthreads();

    const float* up0 = Us + (ks << 3) * 256 + (j << 2);
    int buf = 0;
    for (int t = 0; t < TT; t++) {
        u64 z2[4][2];
#pragma unroll
        for (int b = 0; b < 4; b++) { z2[b][0] = 0ull; z2[b][1] = 0ull; }

        ulonglong2 xv[4];
        if (ks == 0) {
#pragma unroll
            for (int b = 0; b < 4; b++)
                xv[b] = *(const ulonglong2*)(g_xw2 + ((size_t)(t * BB + brow + b) << 8) + (j << 2));
        }
        const float* hb = hd + buf * 512;
        {   // smem rows: krow = ks*16 + [0,8)
            const float* hp = hb + (ks << 4) * 8;
            const float* up = up0;
#pragma unroll
            for (int r = 0; r < 8; r++) {
                ulonglong2 hA = *(const ulonglong2*)(hp + (r << 3));
                ulonglong2 hB = *(const ulonglong2*)(hp + (r << 3) + 4);
                ulonglong2 uv = *(const ulonglong2*)(up);
                up += 256;
                fma2(z2[0][0], hA.x, uv.x); fma2(z2[0][1], hA.x, uv.y);
                fma2(z2[1][0], hA.y, uv.x); fma2(z2[1][1], hA.y, uv.y);
                fma2(z2[2][0], hB.x, uv.x); fma2(z2[2][1], hB.x, uv.y);
                fma2(z2[3][0], hB.y, uv.x); fma2(z2[3][1], hB.y, uv.y);
            }
        }
        {   // register rows: krow = ks*16 + [8,16)
            const float* hp = hb + rbase * 8;
#pragma unroll
            for (int r = 0; r < 8; r++) {
                ulonglong2 hA = *(const ulonglong2*)(hp + (r << 3));
                ulonglong2 hB = *(const ulonglong2*)(hp + (r << 3) + 4);
                fma2(z2[0][0], hA.x, uw[r].x); fma2(z2[0][1], hA.x, uw[r].y);
                fma2(z2[1][0], hA.y, uw[r].x); fma2(z2[1][1], hA.y, uw[r].y);
                fma2(z2[2][0], hB.x, uw[r].x); fma2(z2[2][1], hB.x, uw[r].y);
                fma2(z2[3][0], hB.y, uw[r].x); fma2(z2[3][1], hB.y, uw[r].y);
            }
        }
        if (ks) {
            float* exq = ex + (ks - 1) * 1280 + j * 20;
#pragma unroll
            for (int b = 0; b < 4; b++)
                *(ulonglong2*)(exq + (b << 2)) = make_ulonglong2(z2[b][0], z2[b][1]);
        }
        __syncthreads();
        if (ks == 0) {
            float* hn = hd + (buf ^ 1) * 512;
            float hv[4];
#pragma unroll
            for (int b = 0; b < 4; b++) {
#pragma unroll
                for (int q = 0; q < 3; q++) {
                    ulonglong2 e = *(const ulonglong2*)(ex + q * 1280 + j * 20 + (b << 2));
                    add2(z2[b][0], e.x);
                    add2(z2[b][1], e.y);
                }
                add2(z2[b][0], xv[b].x);
                add2(z2[b][1], xv[b].y);
                float2 p0 = unpack2(z2[b][0]);
                float2 p1 = unpack2(z2[b][1]);
                float ig = sigf(p0.x);
                float fg = sigf(p0.y);
                float gg = fmaxf(p1.x, 0.f);
                float og = sigf(p1.y);
                cc[b] = fg * cc[b] + ig * gg;
                hv[b] = og * fmaxf(cc[b], 0.f);
                if (t == TT - 1)
                    g_h2[((brow + b) << 6) + j] = hv[b];
            }
            *(ulonglong2*)(hn + (j << 3)) =
                make_ulonglong2(pack2(hv[0], hv[0]), pack2(hv[1], hv[1]));
            *(ulonglong2*)(hn + (j << 3) + 4) =
                make_ulonglong2(pack2(hv[2], hv[2]), pack2(hv[3], hv[3]));
        }
        __syncthreads();
        buf ^= 1;
    }
}

// ---------------------------------------------------------------------------
// Dense head: out[b] = (h2[b] @ Wd1 + bd1) @ Wd2 + bd2
// ---------------------------------------------------------------------------
__global__ void dense_kernel(const float* __restrict__ Wd1, const float* __restrict__ bd1,
                             const float* __restrict__ Wd2, const float* __restrict__ bd2,
                             float* __restrict__ out)
{
    int b = blockIdx.x * blockDim.x + threadIdx.x;
    if (b >= BB) return;
    float h[H2];
#pragma unroll
    for (int k = 0; k < H2; k++) h[k] = g_h2[(b << 6) + k];
    float acc = bd2[0];
    for (int d = 0; d < 25; d++) {
        float s = bd1[d];
#pragma unroll
        for (int k = 0; k < H2; k++) s += h[k] * Wd1[k * 25 + d];
        acc += s * Wd2[d];
    }
    out[b] = acc;
}

// ---------------------------------------------------------------------------
// Launch
// ---------------------------------------------------------------------------
extern "C" void kernel_launch(void* const* d_in, const int* in_sizes, int n_in,
                              void* d_out, int out_size)
{
    const float* x   = (const float*)d_in[0];
    const float* W1  = (const float*)d_in[1];
    const float* U1  = (const float*)d_in[2];
    const float* b1  = (const float*)d_in[3];
    const float* W2  = (const float*)d_in[4];
    const float* U2  = (const float*)d_in[5];
    const float* b2  = (const float*)d_in[6];
    const float* Wd1 = (const float*)d_in[7];
    const float* bd1 = (const float*)d_in[8];
    const float* Wd2 = (const float*)d_in[9];
    const float* bd2 = (const float*)d_in[10];
    float* out = (float*)d_out;

    cudaFuncSetAttribute(gemm_kernel, cudaFuncAttributeMaxDynamicSharedMemorySize, GEMM_SMEM);
    cudaFuncSetAttribute(rec1_kernel, cudaFuncAttributeMaxDynamicSharedMemorySize, REC1_SMEM);
    cudaFuncSetAttribute(rec2_kernel, cudaFuncAttributeMaxDynamicSharedMemorySize, REC2_SMEM);

    float *pWp1, *pbp1, *pWp2, *pbp2, *pxw1, *pxw2, *ph1;
    cudaGetSymbolAddress((void**)&pWp1, g_Wp1);
    cudaGetSymbolAddress((void**)&pbp1, g_bp1);
    cudaGetSymbolAddress((void**)&pWp2, g_Wp2);
    cudaGetSymbolAddress((void**)&pbp2, g_bp2);
    cudaGetSymbolAddress((void**)&pxw1, g_xw1);
    cudaGetSymbolAddress((void**)&pxw2, g_xw2);
    cudaGetSymbolAddress((void**)&ph1,  g_h1);

    // 1. permute weights into gate-interleaved layout
    prep_kernel<<<256, 256>>>(W1, U1, b1, W2, U2, b2);

    // 2. xW1: x[b][t][:] @ Wp1 -> g_xw1[t][b][:]
    gemm_kernel<<<dim3((TT * BB) / 128, G1 / 128), 256, GEMM_SMEM>>>(
        x, pWp1, pbp1, pxw1, FF, TT * FF, FF, G1);

    // 3. layer-1 recurrence -> g_h1[t][b][:]
    rec1_kernel<<<BB / 4, 256, REC1_SMEM>>>();

    // 4. xW2: h1[t][b][:] @ Wp2 -> g_xw2[t][b][:]
    gemm_kernel<<<dim3((TT * BB) / 128, G2 / 128), 256, GEMM_SMEM>>>(
        ph1, pWp2, pbp2, pxw2, BB * H1, H1, H1, G2);

    // 5. layer-2 recurrence -> g_h2[b][:]
    rec2_kernel<<<BB / 4, 256, REC2_SMEM>>>();

    // 6. dense head
    dense_kernel<<<2, 256>>>(Wd1, bd1, Wd2, bd2, out);
}

// round 5
// speedup vs baseline: 1.0966x; 1.0047x over previous
#include <cuda_runtime.h>
#include <cstddef>

// Problem constants
#define BB 512   // batch
#define TT 512   // timesteps
#define FF 64    // input features
#define H1 128   // layer1 hidden
#define G1 512   // 4*H1
#define H2 64    // layer2 hidden
#define G2 256   // 4*H2

typedef unsigned long long u64;

// ---------------------------------------------------------------------------
// Packed fp32x2 helpers (sm_103a): 2 IEEE fp32 FMAs per instruction.
// ---------------------------------------------------------------------------
__device__ __forceinline__ u64 pack2(float lo, float hi) {
    u64 r; asm("mov.b64 %0, {%1, %2};" : "=l"(r) : "f"(lo), "f"(hi)); return r;
}
__device__ __forceinline__ float2 unpack2(u64 v) {
    float2 f; asm("mov.b64 {%0, %1}, %2;" : "=f"(f.x), "=f"(f.y) : "l"(v)); return f;
}
__device__ __forceinline__ void fma2(u64& d, u64 a, u64 b) {
    asm("fma.rn.f32x2 %0, %1, %2, %0;" : "+l"(d) : "l"(a), "l"(b));
}
__device__ __forceinline__ void add2(u64& d, u64 a) {
    asm("add.rn.f32x2 %0, %0, %1;" : "+l"(d) : "l"(a));
}

// ---------------------------------------------------------------------------
// Device scratch
// ---------------------------------------------------------------------------
__device__ float g_Wp1[FF * G1];        // W1 permuted: [f][j*4+gate]
__device__ float g_bp1[G1];
__device__ float g_Up1[H1 * G1];        // U1 permuted: [k][j*4+gate]
__device__ float g_Wp2[H1 * G2];
__device__ float g_bp2[G2];
__device__ float g_Up2[H2 * G2];
__device__ float g_xw1[(size_t)TT * BB * G1];  // [t][b][j*4+gate]
__device__ float g_h1[(size_t)TT * BB * H1];   // [t][b][j]
__device__ float g_xw2[(size_t)TT * BB * G2];  // [t][b][j*4+gate]
__device__ float g_h2[BB * H2];                // final layer2 h

__device__ __forceinline__ float sigf(float x) {
    return __fdividef(1.0f, 1.0f + __expf(-x));
}

// ---------------------------------------------------------------------------
// Prep: permute weights so column n = j*4 + gate  (gate order i,f,g,o)
// ---------------------------------------------------------------------------
__global__ void prep_kernel(const float* __restrict__ W1, const float* __restrict__ U1,
                            const float* __restrict__ b1, const float* __restrict__ W2,
                            const float* __restrict__ U2, const float* __restrict__ b2)
{
    int i = blockIdx.x * blockDim.x + threadIdx.x;
    if (i < FF * G1) {
        int f = i >> 9, n = i & 511;
        int j = n >> 2, gi = n & 3;
        g_Wp1[i] = W1[f * G1 + gi * H1 + j];
    }
    if (i < G1) {
        int j = i >> 2, gi = i & 3;
        g_bp1[i] = b1[gi * H1 + j];
    }
    if (i < H1 * G1) {
        int k = i >> 9, n = i & 511;
        int j = n >> 2, gi = n & 3;
        g_Up1[i] = U1[k * G1 + gi * H1 + j];
    }
    if (i < H1 * G2) {
        int k = i >> 8, n = i & 255;
        int j = n >> 2, gi = n & 3;
        g_Wp2[i] = W2[k * G2 + gi * H2 + j];
    }
    if (i < G2) {
        int j = i >> 2, gi = i & 3;
        g_bp2[i] = b2[gi * H2 + j];
    }
    if (i < H2 * G2) {
        int k = i >> 8, n = i & 255;
        int j = n >> 2, gi = n & 3;
        g_Up2[i] = U2[k * G2 + gi * H2 + j];
    }
}

// ---------------------------------------------------------------------------
// FMA2 GEMM, occupancy-2:  C[m][n] = sum_k A_row(m)[k] * W[k][n] + bias[n]
// CTA tile 128(m) x 128(n), 256 threads, per-thread 8(m)x8(n) = 32 FMA2/k.
// 2 CTAs / SM (regs ~105, smem 49.7KB) -> 16 warps for issue hiding.
// A: k-major natural (m-pairs in LDS.128; 2 addrs/warp -> near-broadcast).
// W: duplicated pairs, swizzled Wd[k][c][tx] so reads are 16B conflict-free.
// ---------------------------------------------------------------------------
#define AS_LD 132                        // padded floats per k-row of A tile
#define GEMM_SMEM ((32 * AS_LD + 32 * 256) * 4)   // 49664 B

__global__ __launch_bounds__(256, 2) void gemm_kernel(
    const float* __restrict__ A, const float* __restrict__ W,
    const float* __restrict__ bias, float* __restrict__ C,
    int sT, int sB, int K, int N)
{
    extern __shared__ float sm[];
    float* As = sm;                  // [32][AS_LD]  k-major, m natural
    float* Wd = sm + 32 * AS_LD;     // [32][4][16][4]: dup pairs, swizzled by tx
    const int tid = threadIdx.x;
    const int tx = tid & 15;         // n group: n = tx*8 .. tx*8+7
    const int ty = tid >> 4;         // m group: m = ty*8 .. ty*8+7
    const int mt = blockIdx.x * 128;
    const int nt = blockIdx.y * 128;

    u64 acc[4][8];
#pragma unroll
    for (int p = 0; p < 4; p++)
#pragma unroll
        for (int q = 0; q < 8; q++) acc[p][q] = 0ull;

    // A loader: thread handles row am = tid&127, k-span kc*16..kc*16+15
    const int am = tid & 127;
    const int kc = tid >> 7;
    const int gm0 = mt + am;
    const int t0 = gm0 >> 9, b0 = gm0 & 511;
    const float* arow = A + (size_t)t0 * sT + (size_t)b0 * sB + (kc << 4);

    for (int kt = 0; kt < K; kt += 32) {
        // ---- A tile: 128 rows x 32 k, transposed into smem (k-major) ----
#pragma unroll
        for (int kq = 0; kq < 4; kq++) {
            float4 v = *(const float4*)(arow + kt + (kq << 2));
            int kk = (kc << 4) + (kq << 2);
            As[(kk + 0) * AS_LD + am] = v.x;
            As[(kk + 1) * AS_LD + am] = v.y;
            As[(kk + 2) * AS_LD + am] = v.z;
            As[(kk + 3) * AS_LD + am] = v.w;
        }
        // ---- W tile: 32 k x 128 n, duplicated + swizzled ----
        {
            int txw = tid & 15;
            int c   = (tid >> 4) & 3;
            int kb  = tid >> 6;          // 0..3
#pragma unroll
            for (int i = 0; i < 8; i++) {
                int k = kb + (i << 2);   // 0..31
                float2 w2 = *(const float2*)(W + (size_t)(kt + k) * N + nt + (txw << 3) + (c << 1));
                *(float4*)(Wd + (k << 8) + (c << 6) + (txw << 2)) =
                    make_float4(w2.x, w2.x, w2.y, w2.y);
            }
        }
        __syncthreads();
        // ---- compute ----
#pragma unroll 4
        for (int k = 0; k < 32; k++) {
            const float* ar = As + k * AS_LD + (ty << 3);
            ulonglong2 a01 = *(const ulonglong2*)(ar);        // m-pairs (0,1),(2,3)
            ulonglong2 a23 = *(const ulonglong2*)(ar + 4);    // m-pairs (4,5),(6,7)
            const float* wr = Wd + (k << 8) + (tx << 2);
            ulonglong2 w01 = *(const ulonglong2*)(wr);
            ulonglong2 w23 = *(const ulonglong2*)(wr + 64);
            ulonglong2 w45 = *(const ulonglong2*)(wr + 128);
            ulonglong2 w67 = *(const ulonglong2*)(wr + 192);
            u64 av[4] = {a01.x, a01.y, a23.x, a23.y};
            u64 wv[8] = {w01.x, w01.y, w23.x, w23.y, w45.x, w45.y, w67.x, w67.y};
#pragma unroll
            for (int p = 0; p < 4; p++)
#pragma unroll
                for (int q = 0; q < 8; q++) fma2(acc[p][q], av[p], wv[q]);
        }
        __syncthreads();
    }

    // ---- epilogue: bias + store ----
    u64 bd[8];
#pragma unroll
    for (int q = 0; q < 8; q++) {
        float bv = bias[nt + (tx << 3) + q];
        bd[q] = pack2(bv, bv);
    }
#pragma unroll
    for (int p = 0; p < 4; p++) {
        float2 f[8];
#pragma unroll
        for (int q = 0; q < 8; q++) {
            add2(acc[p][q], bd[q]);
            f[q] = unpack2(acc[p][q]);
        }
        int m0 = mt + (ty << 3) + (p << 1);
        float* c0 = C + (size_t)m0 * N + nt + (tx << 3);
        float* c1 = c0 + N;
        *(float4*)(c0)     = make_float4(f[0].x, f[1].x, f[2].x, f[3].x);
        *(float4*)(c0 + 4) = make_float4(f[4].x, f[5].x, f[6].x, f[7].x);
        *(float4*)(c1)     = make_float4(f[0].y, f[1].y, f[2].y, f[3].y);
        *(float4*)(c1 + 4) = make_float4(f[4].y, f[5].y, f[6].y, f[7].y);
    }
}

// ---------------------------------------------------------------------------
// Layer-1 recurrence (f32x2). 128 CTAs x 256 threads; CTA owns 4 batch rows.
// thread = (j in [0,128), ks in {0,1}); ks splits the K=128 reduction.
// Per ks-half: 32 U rows in smem, 32 in registers. h kept in smem as
// duplicated pairs {h,h} (warp-uniform address -> broadcast read).
// ---------------------------------------------------------------------------
#define REC1_SMEM ((64 * 512 + 2 * 128 * 8 + 128 * 20) * 4)  // 149504 B

__global__ __launch_bounds__(256, 1) void rec1_kernel()
{
    extern __shared__ float sm[];
    float* Us = sm;                  // [64][512]: s<32 -> k=s (ks0), s>=32 -> k=s+32 (ks1)
    float* hd = sm + 64 * 512;       // [2][128][8]: per k-row {h0,h0,h1,h1,h2,h2,h3,h3}
    float* ex = hd + 2 * 128 * 8;    // [128][20]: ks=1 partials (padded stride)

    const int tid  = threadIdx.x;
    const int j    = tid & 127;
    const int ks   = tid >> 7;
    const int brow = blockIdx.x << 2;

    // cooperative load of smem-resident U rows
    for (int i = tid; i < 64 * 128; i += 256) {
        int s = i >> 7;
        int c = (i & 127) << 2;
        int krow = (s < 32) ? s : (s + 32);
        *(float4*)(Us + s * 512 + c) = *(const float4*)(g_Up1 + krow * 512 + c);
    }
    // register-resident U rows (gate pairs)
    const int rbase = ks * 64 + 32;
    ulonglong2 uw[32];
#pragma unroll
    for (int r = 0; r < 32; r++)
        uw[r] = *(const ulonglong2*)(g_Up1 + (rbase + r) * 512 + (j << 2));
    for (int i = tid; i < 2 * 128 * 8; i += 256) hd[i] = 0.f;  // h0 = 0
    float cc[4] = {0.f, 0.f, 0.f, 0.f};
    __syncthreads();

    const float* up0 = Us + (ks * 32) * 512 + (j << 2);
    int buf = 0;
    for (int t = 0; t < TT; t++) {
        u64 z2[4][2];
#pragma unroll
        for (int b = 0; b < 4; b++) { z2[b][0] = 0ull; z2[b][1] = 0ull; }

        ulonglong2 xv[4];
        if (ks == 0) {  // issue early; consumed after the FMA loop
#pragma unroll
            for (int b = 0; b < 4; b++)
                xv[b] = *(const ulonglong2*)(g_xw1 + ((size_t)(t * BB + brow + b) << 9) + (j << 2));
        }

        const float* hb = hd + buf * 1024;
        {   // smem U rows: k = ks*64 + [0,32)
            const float* hp = hb + (ks * 64) * 8;
            const float* up = up0;
#pragma unroll 4
            for (int r = 0; r < 32; r++) {
                ulonglong2 hA = *(const ulonglong2*)(hp + (r << 3));      // {h0,h0},{h1,h1}
                ulonglong2 hB = *(const ulonglong2*)(hp + (r << 3) + 4);  // {h2,h2},{h3,h3}
                ulonglong2 uv = *(const ulonglong2*)(up);
                up += 512;
                fma2(z2[0][0], hA.x, uv.x); fma2(z2[0][1], hA.x, uv.y);
                fma2(z2[1][0], hA.y, uv.x); fma2(z2[1][1], hA.y, uv.y);
                fma2(z2[2][0], hB.x, uv.x); fma2(z2[2][1], hB.x, uv.y);
                fma2(z2[3][0], hB.y, uv.x); fma2(z2[3][1], hB.y, uv.y);
            }
        }
        {   // register U rows: k = ks*64 + [32,64)
            const float* hp = hb + rbase * 8;
#pragma unroll
            for (int r = 0; r < 32; r++) {
                ulonglong2 hA = *(const ulonglong2*)(hp + (r << 3));
                ulonglong2 hB = *(const ulonglong2*)(hp + (r << 3) + 4);
                fma2(z2[0][0], hA.x, uw[r].x); fma2(z2[0][1], hA.x, uw[r].y);
                fma2(z2[1][0], hA.y, uw[r].x); fma2(z2[1][1], hA.y, uw[r].y);
                fma2(z2[2][0], hB.x, uw[r].x); fma2(z2[2][1], hB.x, uw[r].y);
                fma2(z2[3][0], hB.y, uw[r].x); fma2(z2[3][1], hB.y, uw[r].y);
            }
        }
        if (ks) {
#pragma unroll
            for (int b = 0; b < 4; b++)
                *(ulonglong2*)(ex + j * 20 + (b << 2)) = make_ulonglong2(z2[b][0], z2[b][1]);
        }
        __syncthreads();
        if (ks == 0) {
            float* hn = hd + (buf ^ 1) * 1024;
            float hv[4];
#pragma unroll
            for (int b = 0; b < 4; b++) {
                ulonglong2 e = *(const ulonglong2*)(ex + j * 20 + (b << 2));
                add2(z2[b][0], e.x);
                add2(z2[b][1], e.y);
                add2(z2[b][0], xv[b].x);
                add2(z2[b][1], xv[b].y);
                float2 p0 = unpack2(z2[b][0]);   // {zi, zf}
                float2 p1 = unpack2(z2[b][1]);   // {zg, zo}
                float ig = sigf(p0.x);
                float fg = sigf(p0.y);
                float gg = fmaxf(p1.x, 0.f);
                float og = sigf(p1.y);
                cc[b] = fg * cc[b] + ig * gg;
                hv[b] = og * fmaxf(cc[b], 0.f);
                g_h1[((size_t)(t * BB + brow + b) << 7) + j] = hv[b];
            }
            *(ulonglong2*)(hn + (j << 3)) =
                make_ulonglong2(pack2(hv[0], hv[0]), pack2(hv[1], hv[1]));
            *(ulonglong2*)(hn + (j << 3) + 4) =
                make_ulonglong2(pack2(hv[2], hv[2]), pack2(hv[3], hv[3]));
        }
        __syncthreads();
        buf ^= 1;
    }
}

// ---------------------------------------------------------------------------
// Layer-2 recurrence (f32x2), 4-way k-split. 128 CTAs x 256 threads.
// thread = (j in [0,64), ks in {0,1,2,3}); ks covers k rows [ks*16, ks*16+16):
// first 8 rows from smem, last 8 from registers. Quarters 1..3 write partials
// to ex; quarter 0 combines + applies gates.
// ---------------------------------------------------------------------------
#define REC2_SMEM ((32 * 256 + 2 * 64 * 8 + 3 * 64 * 20) * 4)  // 52480 B

__global__ __launch_bounds__(256, 1) void rec2_kernel()
{
    extern __shared__ float sm[];
    float* Us = sm;                  // [32][256]: s = q*8+r  <->  krow = q*16+r
    float* hd = sm + 32 * 256;       // [2][64][8]
    float* ex = hd + 2 * 64 * 8;     // [3][64][20]

    const int tid  = threadIdx.x;
    const int j    = tid & 63;
    const int ks   = tid >> 6;       // 0..3
    const int brow = blockIdx.x << 2;

    // cooperative load of smem-resident U rows (8 per quarter)
    for (int i = tid; i < 32 * 64; i += 256) {
        int s = i >> 6;
        int c = (i & 63) << 2;
        int krow = ((s >> 3) << 4) + (s & 7);
        *(float4*)(Us + s * 256 + c) = *(const float4*)(g_Up2 + krow * 256 + c);
    }
    // register rows: krow = ks*16 + 8 + r
    const int rbase = (ks << 4) + 8;
    ulonglong2 uw[8];
#pragma unroll
    for (int r = 0; r < 8; r++)
        uw[r] = *(const ulonglong2*)(g_Up2 + (rbase + r) * 256 + (j << 2));
    for (int i = tid; i < 2 * 64 * 8; i += 256) hd[i] = 0.f;
    float cc[4] = {0.f, 0.f, 0.f, 0.f};
    __syncthreads();

    const float* up0 = Us + (ks << 3) * 256 + (j << 2);
    int buf = 0;
    for (int t = 0; t < TT; t++) {
        u64 z2[4][2];
#pragma unroll
        for (int b = 0; b < 4; b++) { z2[b][0] = 0ull; z2[b][1] = 0ull; }

        ulonglong2 xv[4];
        if (ks == 0) {
#pragma unroll
            for (int b = 0; b < 4; b++)
                xv[b] = *(const ulonglong2*)(g_xw2 + ((size_t)(t * BB + brow + b) << 8) + (j << 2));
        }
        const float* hb = hd + buf * 512;
        {   // smem rows: krow = ks*16 + [0,8)
            const float* hp = hb + (ks << 4) * 8;
            const float* up = up0;
#pragma unroll
            for (int r = 0; r < 8; r++) {
                ulonglong2 hA = *(const ulonglong2*)(hp + (r << 3));
                ulonglong2 hB = *(const ulonglong2*)(hp + (r << 3) + 4);
                ulonglong2 uv = *(const ulonglong2*)(up);
                up += 256;
                fma2(z2[0][0], hA.x, uv.x); fma2(z2[0][1], hA.x, uv.y);
                fma2(z2[1][0], hA.y, uv.x); fma2(z2[1][1], hA.y, uv.y);
                fma2(z2[2][0], hB.x, uv.x); fma2(z2[2][1], hB.x, uv.y);
                fma2(z2[3][0], hB.y, uv.x); fma2(z2[3][1], hB.y, uv.y);
            }
        }
        {   // register rows: krow = ks*16 + [8,16)
            const float* hp = hb + rbase * 8;
#pragma unroll
            for (int r = 0; r < 8; r++) {
                ulonglong2 hA = *(const ulonglong2*)(hp + (r << 3));
                ulonglong2 hB = *(const ulonglong2*)(hp + (r << 3) + 4);
                fma2(z2[0][0], hA.x, uw[r].x); fma2(z2[0][1], hA.x, uw[r].y);
                fma2(z2[1][0], hA.y, uw[r].x); fma2(z2[1][1], hA.y, uw[r].y);
                fma2(z2[2][0], hB.x, uw[r].x); fma2(z2[2][1], hB.x, uw[r].y);
                fma2(z2[3][0], hB.y, uw[r].x); fma2(z2[3][1], hB.y, uw[r].y);
            }
        }
        if (ks) {
            float* exq = ex + (ks - 1) * 1280 + j * 20;
#pragma unroll
            for (int b = 0; b < 4; b++)
                *(ulonglong2*)(exq + (b << 2)) = make_ulonglong2(z2[b][0], z2[b][1]);
        }
        __syncthreads();
        if (ks == 0) {
            float* hn = hd + (buf ^ 1) * 512;
            float hv[4];
#pragma unroll
            for (int b = 0; b < 4; b++) {
#pragma unroll
                for (int q = 0; q < 3; q++) {
                    ulonglong2 e = *(const ulonglong2*)(ex + q * 1280 + j * 20 + (b << 2));
                    add2(z2[b][0], e.x);
                    add2(z2[b][1], e.y);
                }
                add2(z2[b][0], xv[b].x);
                add2(z2[b][1], xv[b].y);
                float2 p0 = unpack2(z2[b][0]);
                float2 p1 = unpack2(z2[b][1]);
                float ig = sigf(p0.x);
                float fg = sigf(p0.y);
                float gg = fmaxf(p1.x, 0.f);
                float og = sigf(p1.y);
                cc[b] = fg * cc[b] + ig * gg;
                hv[b] = og * fmaxf(cc[b], 0.f);
                if (t == TT - 1)
                    g_h2[((brow + b) << 6) + j] = hv[b];
            }
            *(ulonglong2*)(hn + (j << 3)) =
                make_ulonglong2(pack2(hv[0], hv[0]), pack2(hv[1], hv[1]));
            *(ulonglong2*)(hn + (j << 3) + 4) =
                make_ulonglong2(pack2(hv[2], hv[2]), pack2(hv[3], hv[3]));
        }
        __syncthreads();
        buf ^= 1;
    }
}

// ---------------------------------------------------------------------------
// Dense head: out[b] = (h2[b] @ Wd1 + bd1) @ Wd2 + bd2
// ---------------------------------------------------------------------------
__global__ void dense_kernel(const float* __restrict__ Wd1, const float* __restrict__ bd1,
                             const float* __restrict__ Wd2, const float* __restrict__ bd2,
                             float* __restrict__ out)
{
    int b = blockIdx.x * blockDim.x + threadIdx.x;
    if (b >= BB) return;
    float h[H2];
#pragma unroll
    for (int k = 0; k < H2; k++) h[k] = g_h2[(b << 6) + k];
    float acc = bd2[0];
    for (int d = 0; d < 25; d++) {
        float s = bd1[d];
#pragma unroll
        for (int k = 0; k < H2; k++) s += h[k] * Wd1[k * 25 + d];
        acc += s * Wd2[d];
    }
    out[b] = acc;
}

// ---------------------------------------------------------------------------
// Launch
// ---------------------------------------------------------------------------
extern "C" void kernel_launch(void* const* d_in, const int* in_sizes, int n_in,
                              void* d_out, int out_size)
{
    const float* x   = (const float*)d_in[0];
    const float* W1  = (const float*)d_in[1];
    const float* U1  = (const float*)d_in[2];
    const float* b1  = (const float*)d_in[3];
    const float* W2  = (const float*)d_in[4];
    const float* U2  = (const float*)d_in[5];
    const float* b2  = (const float*)d_in[6];
    const float* Wd1 = (const float*)d_in[7];
    const float* bd1 = (const float*)d_in[8];
    const float* Wd2 = (const float*)d_in[9];
    const float* bd2 = (const float*)d_in[10];
    float* out = (float*)d_out;

    cudaFuncSetAttribute(gemm_kernel, cudaFuncAttributeMaxDynamicSharedMemorySize, GEMM_SMEM);
    cudaFuncSetAttribute(rec1_kernel, cudaFuncAttributeMaxDynamicSharedMemorySize, REC1_SMEM);
    cudaFuncSetAttribute(rec2_kernel, cudaFuncAttributeMaxDynamicSharedMemorySize, REC2_SMEM);

    float *pWp1, *pbp1, *pWp2, *pbp2, *pxw1, *pxw2, *ph1;
    cudaGetSymbolAddress((void**)&pWp1, g_Wp1);
    cudaGetSymbolAddress((void**)&pbp1, g_bp1);
    cudaGetSymbolAddress((void**)&pWp2, g_Wp2);
    cudaGetSymbolAddress((void**)&pbp2, g_bp2);
    cudaGetSymbolAddress((void**)&pxw1, g_xw1);
    cudaGetSymbolAddress((void**)&pxw2, g_xw2);
    cudaGetSymbolAddress((void**)&ph1,  g_h1);

    // 1. permute weights into gate-interleaved layout
    prep_kernel<<<256, 256>>>(W1, U1, b1, W2, U2, b2);

    // 2. xW1: x[b][t][:] @ Wp1 -> g_xw1[t][b][:]
    gemm_kernel<<<dim3((TT * BB) / 128, G1 / 128), 256, GEMM_SMEM>>>(
        x, pWp1, pbp1, pxw1, FF, TT * FF, FF, G1);

    // 3. layer-1 recurrence -> g_h1[t][b][:]
    rec1_kernel<<<BB / 4, 256, REC1_SMEM>>>();

    // 4. xW2: h1[t][b][:] @ Wp2 -> g_xw2[t][b][:]
    gemm_kernel<<<dim3((TT * BB) / 128, G2 / 128), 256, GEMM_SMEM>>>(
        ph1, pWp2, pbp2, pxw2, BB * H1, H1, H1, G2);

    // 5. layer-2 recurrence -> g_h2[b][:]
    rec2_kernel<<<BB / 4, 256, REC2_SMEM>>>();

    // 6. dense head
    dense_kernel<<<2, 256>>>(Wd1, bd1, Wd2, bd2, out);
}